// round 1
// baseline (speedup 1.0000x reference)
#include <cuda_runtime.h>
#include <math.h>

// Problem constants
#define BATCH   64
#define DIM     256
#define HWSZ    1024           // 32*32
#define NTOK    65536          // 64*1024
#define NCODE   1024
#define CHW     (DIM*HWSZ)     // 262144

#define TM      128            // tokens per block
#define TN      128            // codes per tile
#define KC      16             // K chunk depth
#define NBLK    (NTOK/TM)      // 512

// Output layout: [loss(1) | quantized(64*256*32*32) | perplexity(1) | idx(65536)]
#define QUANT_OFF 1
#define PERP_OFF  (1 + BATCH*CHW)          // 4194305
#define IDX_OFF   (PERP_OFF + 1)           // 4194306

__device__ float g_c2[NCODE];
__device__ int   g_counts[NCODE];
__device__ float g_partials[NBLK];

struct SmemA {
    float As[DIM * TM];     // [d][m], 128 KB
    float Bs[KC * TN];      // [k][c], 8 KB
    float c2s[NCODE];       // 4 KB
    float t1s[TM];          // 0.5 KB
    float redv[TM * 16];    // 8 KB
    int   redi[TM * 16];    // 8 KB
    int   best[TM];         // 0.5 KB
    float rbuf[256];        // 1 KB
};

// ---------------------------------------------------------------------------
// Prep: codebook row norms + zero counts (runs every launch; graph-safe)
// ---------------------------------------------------------------------------
__global__ void vq_prep_kernel(const float* __restrict__ cb) {
    int k = blockIdx.x * 256 + threadIdx.x;
    if (k < NCODE) {
        const float* row = cb + (size_t)k * DIM;
        float s = 0.f;
        #pragma unroll 8
        for (int d = 0; d < DIM; ++d) s = fmaf(row[d], row[d], s);
        g_c2[k]     = s;
        g_counts[k] = 0;
    }
}

// ---------------------------------------------------------------------------
// Main fused kernel: distances + argmin + idx + counts + quantized + SSE
// ---------------------------------------------------------------------------
__global__ __launch_bounds__(256, 1)
void vq_main_kernel(const float* __restrict__ x,
                    const float* __restrict__ cb,
                    float* __restrict__ out) {
    extern __shared__ char smem_raw[];
    SmemA& sm = *reinterpret_cast<SmemA*>(smem_raw);

    const int t  = threadIdx.x;
    const int n0 = blockIdx.x * TM;
    const int b  = n0 >> 10;         // batch index (128 | 1024 so uniform per block)
    const int hw0 = n0 & 1023;

    // ---- Load A tile [d][m] (coalesced along hw), and c2 to smem ----
    {
        const float* base = x + (size_t)b * CHW + hw0;
        const float4* base4 = reinterpret_cast<const float4*>(base);
        // 256 d-rows * 32 float4 each = 8192 float4 loads
        for (int i = t; i < DIM * (TM / 4); i += 256) {
            int d  = i >> 5;          // /32
            int mq = i & 31;
            float4 v = base4[(d * HWSZ) / 4 + mq];
            float* dst = &sm.As[d * TM + mq * 4];
            dst[0] = v.x; dst[1] = v.y; dst[2] = v.z; dst[3] = v.w;
        }
        for (int i = t; i < NCODE; i += 256) sm.c2s[i] = g_c2[i];
    }
    __syncthreads();

    // ---- Token norms t1 = ||x||^2 (sequential over d, fp32) ----
    if (t < TM) {
        float s = 0.f;
        #pragma unroll 8
        for (int d = 0; d < DIM; ++d) {
            float v = sm.As[d * TM + t];
            s = fmaf(v, v, s);
        }
        sm.t1s[t] = s;
    }
    __syncthreads();

    // ---- Micro-tile assignment: 16x16 threads, each 8 tokens x 8 codes ----
    const int r    = t >> 4;          // 0..15
    const int cidx = t & 15;          // 0..15
    const int m0   = r * 8;
    const int c0   = cidx * 8;

    float bv[8];
    int   bi[8];
    #pragma unroll
    for (int i = 0; i < 8; ++i) { bv[i] = 3.4e38f; bi[i] = 0x7fffffff; }

    const float4* cb4 = reinterpret_cast<const float4*>(cb);
    const float4* As4 = reinterpret_cast<const float4*>(sm.As);
    const float4* Bs4 = reinterpret_cast<const float4*>(sm.Bs);

    for (int kt = 0; kt < NCODE / TN; ++kt) {            // 8 code tiles
        float acc[8][8];
        #pragma unroll
        for (int i = 0; i < 8; ++i)
            #pragma unroll
            for (int j = 0; j < 8; ++j) acc[i][j] = 0.f;

        for (int kk = 0; kk < DIM; kk += KC) {
            __syncthreads();  // previous Bs consumed
            // Cooperative load Bs[k][c]: 128 codes x 16 d = 512 float4
            #pragma unroll
            for (int p = 0; p < 2; ++p) {
                int i  = t + p * 256;
                int c  = i >> 2;
                int d4 = i & 3;
                float4 v = cb4[(size_t)(kt * TN + c) * (DIM / 4) + (kk >> 2) + d4];
                sm.Bs[(d4 * 4 + 0) * TN + c] = v.x;
                sm.Bs[(d4 * 4 + 1) * TN + c] = v.y;
                sm.Bs[(d4 * 4 + 2) * TN + c] = v.z;
                sm.Bs[(d4 * 4 + 3) * TN + c] = v.w;
            }
            __syncthreads();

            #pragma unroll
            for (int k = 0; k < KC; ++k) {
                float4 a0 = As4[((kk + k) * TM + m0) >> 2];
                float4 a1 = As4[((kk + k) * TM + m0 + 4) >> 2];
                float4 b0 = Bs4[(k * TN + c0) >> 2];
                float4 b1 = Bs4[(k * TN + c0 + 4) >> 2];
                float av[8] = {a0.x, a0.y, a0.z, a0.w, a1.x, a1.y, a1.z, a1.w};
                float bw[8] = {b0.x, b0.y, b0.z, b0.w, b1.x, b1.y, b1.z, b1.w};
                #pragma unroll
                for (int i = 0; i < 8; ++i)
                    #pragma unroll
                    for (int j = 0; j < 8; ++j)
                        acc[i][j] = fmaf(av[i], bw[j], acc[i][j]);
            }
        }

        // ---- distances for this tile, update running argmin ----
        #pragma unroll
        for (int i = 0; i < 8; ++i) {
            float t1 = sm.t1s[m0 + i];
            #pragma unroll
            for (int j = 0; j < 8; ++j) {
                int code = kt * TN + c0 + j;
                float s  = t1 + sm.c2s[code];          // fl(t1 + t2)
                float dv = fmaf(-2.f, acc[i][j], s);   // fl(s - 2*acc): same rounding as ref
                if (dv < bv[i] || (dv == bv[i] && code < bi[i])) {
                    bv[i] = dv; bi[i] = code;
                }
            }
        }
    }

    // ---- Cross-thread argmin reduction (16 candidates per token) ----
    #pragma unroll
    for (int i = 0; i < 8; ++i) {
        sm.redv[(m0 + i) * 16 + cidx] = bv[i];
        sm.redi[(m0 + i) * 16 + cidx] = bi[i];
    }
    __syncthreads();

    if (t < TM) {
        float v = sm.redv[t * 16];
        int  id = sm.redi[t * 16];
        #pragma unroll
        for (int c = 1; c < 16; ++c) {
            float vv = sm.redv[t * 16 + c];
            int   ii = sm.redi[t * 16 + c];
            if (vv < v || (vv == v && ii < id)) { v = vv; id = ii; }
        }
        sm.best[t] = id;
        out[IDX_OFF + n0 + t] = (float)id;
        atomicAdd(&g_counts[id], 1);
    }
    __syncthreads();

    // ---- Epilogue: quantized write (NCHW, coalesced) + SSE ----
    {
        const int m    = t & 127;
        const int half = t >> 7;
        const int bst  = sm.best[m];
        const float* qrow = cb + (size_t)bst * DIM;
        float* outq = out + QUANT_OFF + (size_t)b * CHW + hw0 + m;
        float sse = 0.f;
        #pragma unroll 4
        for (int dd = 0; dd < 128; ++dd) {
            int d = half * 128 + dd;
            float q  = qrow[d];
            float xv = sm.As[d * TM + m];
            float df = q - xv;
            sse = fmaf(df, df, sse);
            outq[(size_t)d * HWSZ] = q;
        }
        sm.rbuf[t] = sse;
    }
    __syncthreads();
    for (int s = 128; s > 0; s >>= 1) {
        if (t < s) sm.rbuf[t] += sm.rbuf[t + s];
        __syncthreads();
    }
    if (t == 0) g_partials[blockIdx.x] = sm.rbuf[0];
}

// ---------------------------------------------------------------------------
// Finalize: loss + perplexity (deterministic reductions)
// ---------------------------------------------------------------------------
__global__ void vq_final_kernel(float* __restrict__ out) {
    __shared__ float buf[256];
    int t = threadIdx.x;

    // SSE total over 512 block partials (fixed order)
    float s = g_partials[t] + g_partials[t + 256];
    buf[t] = s;
    __syncthreads();
    for (int k = 128; k > 0; k >>= 1) {
        if (t < k) buf[t] += buf[t + k];
        __syncthreads();
    }
    if (t == 0) {
        float mse = buf[0] / (float)(BATCH * CHW);
        out[0] = mse + 0.25f * mse;   // q_latent + COMMITMENT_COST * e_latent
    }
    __syncthreads();

    // Perplexity
    float ps = 0.f;
    for (int k = t; k < NCODE; k += 256) {
        float p = (float)g_counts[k] * (1.0f / (float)NTOK);
        ps += p * logf(p + 1e-10f);
    }
    buf[t] = ps;
    __syncthreads();
    for (int k = 128; k > 0; k >>= 1) {
        if (t < k) buf[t] += buf[t + k];
        __syncthreads();
    }
    if (t == 0) out[PERP_OFF] = expf(-buf[0]);
}

// ---------------------------------------------------------------------------
extern "C" void kernel_launch(void* const* d_in, const int* in_sizes, int n_in,
                              void* d_out, int out_size) {
    const float* x  = (const float*)d_in[0];   // [64,256,32,32] f32
    const float* cb = (const float*)d_in[1];   // [1024,256] f32
    float* out = (float*)d_out;

    cudaFuncSetAttribute(vq_main_kernel,
                         cudaFuncAttributeMaxDynamicSharedMemorySize,
                         (int)sizeof(SmemA));

    vq_prep_kernel<<<4, 256>>>(cb);
    vq_main_kernel<<<NBLK, 256, sizeof(SmemA)>>>(x, cb, out);
    vq_final_kernel<<<1, 256>>>(out);
}